// round 15
// baseline (speedup 1.0000x reference)
#include <cuda_runtime.h>
#include <cuda_bf16.h>
#include <cuda_fp16.h>
#include <cstdint>

#define NODES   4096
#define GRAPHS  128
#define GSIZE   32
#define DIN     128
#define HK      128     // HEADS*KEY_SIZE
#define QKVN    384     // 3*HK
#define DOUT    4096

// bf16 hi/lo split operands for the precision-critical QKV GEMM
__device__ __align__(16) __nv_bfloat16 g_Whi[QKVN * DIN];    // [Wq|Wk|Wv]^T K-major
__device__ __align__(16) __nv_bfloat16 g_Wlo[QKVN * DIN];
__device__ __align__(16) float         g_bqkv[QKVN];
// fp16 single-precision-pass operands for the output GEMM
__device__ __align__(16) __half        g_Af16[NODES * HK];
__device__ __align__(16) __half        g_Bf16[DOUT * HK];    // WoT K-major

__device__ __forceinline__ uint32_t smem_u32(const void* p) {
    uint32_t a;
    asm("{ .reg .u64 t; cvta.to.shared.u64 t, %1; cvt.u32.u64 %0, t; }"
        : "=r"(a) : "l"(p));
    return a;
}
__device__ __forceinline__ void ldsm_x4(uint32_t* d, uint32_t addr) {
    asm volatile("ldmatrix.sync.aligned.m8n8.x4.shared.b16 {%0,%1,%2,%3}, [%4];"
                 : "=r"(d[0]), "=r"(d[1]), "=r"(d[2]), "=r"(d[3]) : "r"(addr));
}
__device__ __forceinline__ void mma16816(float* c, const uint32_t* a, const uint32_t* b) {
    asm volatile(
        "mma.sync.aligned.m16n8k16.row.col.f32.bf16.bf16.f32 "
        "{%0,%1,%2,%3}, {%4,%5,%6,%7}, {%8,%9}, {%0,%1,%2,%3};"
        : "+f"(c[0]), "+f"(c[1]), "+f"(c[2]), "+f"(c[3])
        : "r"(a[0]), "r"(a[1]), "r"(a[2]), "r"(a[3]), "r"(b[0]), "r"(b[1]));
}
__device__ __forceinline__ void mma16816h(float* c, const uint32_t* a, const uint32_t* b) {
    asm volatile(
        "mma.sync.aligned.m16n8k16.row.col.f32.f16.f16.f32 "
        "{%0,%1,%2,%3}, {%4,%5,%6,%7}, {%8,%9}, {%0,%1,%2,%3};"
        : "+f"(c[0]), "+f"(c[1]), "+f"(c[2]), "+f"(c[3])
        : "r"(a[0]), "r"(a[1]), "r"(a[2]), "r"(a[3]), "r"(b[0]), "r"(b[1]));
}
__device__ __forceinline__ void cp16(uint32_t smem_addr, const void* gptr) {
    asm volatile("cp.async.cg.shared.global [%0], [%1], 16;"
                 :: "r"(smem_addr), "l"(gptr) : "memory");
}
__device__ __forceinline__ void split_bf16(float x, __nv_bfloat16& h, __nv_bfloat16& l) {
    h = __float2bfloat16(x);
    l = __float2bfloat16(x - __bfloat162float(h));
}

#define ASTRIDE 136                     // 16b elems per smem row (odd 16B units)
#define ROWB    (ASTRIDE * 2)           // 272 bytes per smem row

// ---------------------------------------------------------------------------
// prep_all: weight conversions (no smem, dense occupancy).
// ---------------------------------------------------------------------------
__global__ __launch_bounds__(256) void prep_all(
    const float* __restrict__ Wq, const float* __restrict__ bq,
    const float* __restrict__ Wk, const float* __restrict__ bk,
    const float* __restrict__ Wv, const float* __restrict__ bv,
    const float* __restrict__ Wo)
{
    const int p   = blockIdx.x;
    const int tid = threadIdx.x;

    if (p < 256) {                      // Wo transpose -> fp16, n coalesced
        const int n  = (p & 15) * 256 + tid;
        const int kc = (p >> 4) * 8;
        __align__(16) __half hf[8];
        #pragma unroll
        for (int j = 0; j < 8; j++)
            hf[j] = __float2half(__ldg(&Wo[(size_t)(kc + j) * DOUT + n]));
        *(uint4*)&g_Bf16[(size_t)n * HK + kc] = *(uint4*)hf;
    } else {                            // Wq|Wk|Wv transpose + bias
        const int idx = (p - 256) * 256 + tid;   // [0, 6144)
        const int n   = idx >> 4;                // [0, 384)
        const int kc  = (idx & 15) * 8;
        const float* W = (n < HK) ? Wq : (n < 2 * HK) ? Wk : Wv;
        const float* b = (n < HK) ? bq : (n < 2 * HK) ? bk : bv;
        const int nl = n & (HK - 1);
        __align__(16) __nv_bfloat16 hb[8];
        __align__(16) __nv_bfloat16 lb[8];
        #pragma unroll
        for (int j = 0; j < 8; j++) {
            float x = __ldg(&W[(size_t)(kc + j) * HK + nl]);
            split_bf16(x, hb[j], lb[j]);
        }
        *(uint4*)&g_Whi[(size_t)n * DIN + kc] = *(uint4*)hb;
        *(uint4*)&g_Wlo[(size_t)n * DIN + kc] = *(uint4*)lb;
        if ((idx & 15) == 0) g_bqkv[n] = __ldg(&b[nl]);
    }
}

// ---------------------------------------------------------------------------
// fused_qkv_attn: TWO graphs per CTA (64 CTAs, 256 threads, M=64).
//  1) stage 64 node rows as bf16 hi/lo (fused convert)
//  2) bf16x3 MMA vs Wqkv in 6 chunks of 64 N-cols (cp.async double-buffered),
//     warp layout 2M x 4N (warp tile 32M x 16N) -> fp32 q|k|v in smem
//  3) softmax attention: 256 jobs (2 graphs x 4 heads x 32 rows) = all threads
// smem: A 34816 + 2 x B 34816 + qkv 98304 = 202752 B.
// ---------------------------------------------------------------------------
#define FBM   64
#define FBN   64
#define FNC   (QKVN / FBN)              // 6 chunks
#define FA_HI 0
#define FA_LO (FBM * ROWB)              // 17408
#define FB    (2 * FBM * ROWB)          // 34816
#define FB_STR (2 * FBN * ROWB)         // 34816 per buffer (hi then lo)
#define FQKV  (FB + 2 * FB_STR)         // 104448
#define F_SMEM (FQKV + FBM * QKVN * 4)  // 202752

__global__ __launch_bounds__(256, 1) void fused_qkv_attn(
    const float* __restrict__ nodes)
{
    extern __shared__ char smem[];
    const uint32_t sbase = smem_u32(smem);
    float* qkv = (float*)(smem + FQKV);
    const int tid  = threadIdx.x;
    const int wid  = tid >> 5;
    const int lane = tid & 31;
    const int row0 = blockIdx.x * FBM;      // first node row of this CTA

    // ---- stage A (64x128 nodes, fused fp32->bf16 hi/lo) ----
    #pragma unroll
    for (int t = 0; t < (FBM * 16) / 256; t++) {
        const int i  = tid + t * 256;
        const int r  = i >> 4;
        const int k8 = i & 15;
        const uint32_t so = (uint32_t)r * ROWB + (uint32_t)k8 * 16;
        const size_t gi = (size_t)(row0 + r) * DIN + k8 * 8;
        const float4 v0 = *(const float4*)&nodes[gi];
        const float4 v1 = *(const float4*)&nodes[gi + 4];
        const float xs[8] = {v0.x, v0.y, v0.z, v0.w, v1.x, v1.y, v1.z, v1.w};
        __align__(16) __nv_bfloat16 hb[8];
        __align__(16) __nv_bfloat16 lb[8];
        #pragma unroll
        for (int j = 0; j < 8; j++) split_bf16(xs[j], hb[j], lb[j]);
        *(uint4*)(smem + FA_HI + so) = *(uint4*)hb;
        *(uint4*)(smem + FA_LO + so) = *(uint4*)lb;
    }

    // ---- prologue: stage B chunk 0 into buffer 0 ----
    #pragma unroll
    for (int t = 0; t < (FBN * 16) / 256; t++) {
        const int i  = tid + t * 256;
        const int r  = i >> 4;
        const int k8 = i & 15;
        const uint32_t so = (uint32_t)r * ROWB + (uint32_t)k8 * 16;
        const size_t gb = (size_t)r * DIN + k8 * 8;
        cp16(sbase + FB + so,              &g_Whi[gb]);
        cp16(sbase + FB + FBN * ROWB + so, &g_Wlo[gb]);
    }
    asm volatile("cp.async.commit_group;" ::: "memory");

    const int wm0 = (wid & 1) * 32;     // 2 M-groups over 64 rows
    const int wn0 = (wid >> 1) * 16;    // 4 N-groups over 64 cols
    const int a_row = lane & 15;
    const int a_col = (lane >> 4) * 8;
    const int b_row = ((lane >> 4) * 8) + (lane & 7);   // paired x4 (n16)
    const int b_col = ((lane >> 3) & 1) * 8;

    int bbuf = 0;
    for (int nc = 0; nc < FNC; nc++) {
        if (nc + 1 < FNC) {
            const uint32_t dst = sbase + FB + (bbuf ^ 1) * FB_STR;
            #pragma unroll
            for (int t = 0; t < (FBN * 16) / 256; t++) {
                const int i  = tid + t * 256;
                const int r  = i >> 4;
                const int k8 = i & 15;
                const uint32_t so = (uint32_t)r * ROWB + (uint32_t)k8 * 16;
                const size_t gb = (size_t)((nc + 1) * FBN + r) * DIN + k8 * 8;
                cp16(dst + so,              &g_Whi[gb]);
                cp16(dst + FBN * ROWB + so, &g_Wlo[gb]);
            }
            asm volatile("cp.async.commit_group;" ::: "memory");
            asm volatile("cp.async.wait_group 1;" ::: "memory");
        } else {
            asm volatile("cp.async.wait_group 0;" ::: "memory");
        }
        __syncthreads();

        const uint32_t bHiBase = sbase + FB + bbuf * FB_STR;
        const uint32_t bLoBase = bHiBase + FBN * ROWB;

        float acc[2][2][4];
        #pragma unroll
        for (int mf = 0; mf < 2; mf++)
            #pragma unroll
            for (int nf = 0; nf < 2; nf++)
                #pragma unroll
                for (int r = 0; r < 4; r++) acc[mf][nf][r] = 0.f;

        #pragma unroll
        for (int ks = 0; ks < 8; ks++) {
            const int k0 = ks * 16;
            uint32_t aHi[2][4], aLo[2][4], bHi[4], bLo[4];
            #pragma unroll
            for (int mf = 0; mf < 2; mf++) {
                const uint32_t off = (uint32_t)(wm0 + mf * 16 + a_row) * ROWB
                                   + (uint32_t)(k0 + a_col) * 2;
                ldsm_x4(aHi[mf], sbase + FA_HI + off);
                ldsm_x4(aLo[mf], sbase + FA_LO + off);
            }
            {
                const uint32_t off = (uint32_t)(wn0 + b_row) * ROWB
                                   + (uint32_t)(k0 + b_col) * 2;
                ldsm_x4(bHi, bHiBase + off);
                ldsm_x4(bLo, bLoBase + off);
            }
            #pragma unroll
            for (int mf = 0; mf < 2; mf++)
                #pragma unroll
                for (int nf = 0; nf < 2; nf++) {
                    mma16816(acc[mf][nf], aHi[mf], &bHi[nf * 2]);
                    mma16816(acc[mf][nf], aHi[mf], &bLo[nf * 2]);
                    mma16816(acc[mf][nf], aLo[mf], &bHi[nf * 2]);
                }
        }

        // write chunk results (+bias) to fp32 qkv smem
        const int er = lane >> 2;
        const int ec = (lane & 3) * 2;
        #pragma unroll
        for (int nf = 0; nf < 2; nf++) {
            const int n = nc * FBN + wn0 + nf * 8 + ec;
            const float2 bv = *(const float2*)&g_bqkv[n];
            #pragma unroll
            for (int mf = 0; mf < 2; mf++) {
                const int m = wm0 + mf * 16 + er;
                float2 v0, v1;
                v0.x = acc[mf][nf][0] + bv.x;
                v0.y = acc[mf][nf][1] + bv.y;
                v1.x = acc[mf][nf][2] + bv.x;
                v1.y = acc[mf][nf][3] + bv.y;
                *(float2*)&qkv[(size_t)m * QKVN + n]       = v0;
                *(float2*)&qkv[(size_t)(m + 8) * QKVN + n] = v1;
            }
        }
        __syncthreads();   // protect buffer reuse by next prefetch (2 bufs)
        bbuf ^= 1;
    }

    // ---- attention phase: 256 jobs = 2 graphs x 4 heads x 32 rows ----
    {
        const int gl = tid >> 7;          // graph-local 0/1
        const int h  = (tid >> 5) & 3;
        const int i  = tid & 31;
        const int rb = gl * 32;           // row base in qkv
        const float* qrow = qkv + (rb + i) * QKVN + h * 32;
        float qv[32];
        #pragma unroll
        for (int k4 = 0; k4 < 8; k4++) {
            const float4 t = *(const float4*)&qrow[k4 * 4];
            qv[k4*4+0] = t.x; qv[k4*4+1] = t.y; qv[k4*4+2] = t.z; qv[k4*4+3] = t.w;
        }
        const float scale = 0.17677669529663687f;
        float lo[GSIZE];
        float mx = -1e30f;
        #pragma unroll 4
        for (int j = 0; j < GSIZE; j++) {
            const float* krow = qkv + (rb + j) * QKVN + HK + h * 32;
            float acc = 0.f;
            #pragma unroll
            for (int k4 = 0; k4 < 8; k4++) {
                const float4 t = *(const float4*)&krow[k4 * 4];
                acc += qv[k4*4+0] * t.x; acc += qv[k4*4+1] * t.y;
                acc += qv[k4*4+2] * t.z; acc += qv[k4*4+3] * t.w;
            }
            acc *= scale;
            lo[j] = acc;
            mx = fmaxf(mx, acc);
        }
        float s = 0.f;
        #pragma unroll
        for (int j = 0; j < GSIZE; j++) { lo[j] = __expf(lo[j] - mx); s += lo[j]; }
        const float inv = 1.f / s;

        float o[32];
        #pragma unroll
        for (int k = 0; k < 32; k++) o[k] = 0.f;
        #pragma unroll 4
        for (int j = 0; j < GSIZE; j++) {
            const float a = lo[j] * inv;
            const float* vrow = qkv + (rb + j) * QKVN + 2 * HK + h * 32;
            #pragma unroll
            for (int k4 = 0; k4 < 8; k4++) {
                const float4 t = *(const float4*)&vrow[k4 * 4];
                o[k4*4+0] += a * t.x; o[k4*4+1] += a * t.y;
                o[k4*4+2] += a * t.z; o[k4*4+3] += a * t.w;
            }
        }
        const size_t base = (size_t)(row0 + rb + i) * HK + h * 32;
        #pragma unroll
        for (int c8 = 0; c8 < 4; c8++) {
            __align__(16) __half hf[8];
            #pragma unroll
            for (int j = 0; j < 8; j++) hf[j] = __float2half(o[c8 * 8 + j]);
            *(uint4*)&g_Af16[base + c8 * 8] = *(uint4*)hf;
        }
    }
}

// ---------------------------------------------------------------------------
// Persistent fp16 out_gemm on grid 148: 512 threads, 16 warps = 4M x 4N,
// warp tile 32x32, B frags via PAIRED ldsm_x4 (half the LDSM issue count).
// A double-buffered, B triple-buffered (mod-3, no trailing barrier).
// smem 174080 B.
// ---------------------------------------------------------------------------
#define BM 128
#define TILE_A  (BM * ROWB)             // 34816 B
#define BN2     128
#define TILE_B2 (BN2 * ROWB)            // 34816 B
#define GRID_P  148
#define NTILES  1024                    // 32 x 32
#define PO_A    0
#define PO_B    (2 * TILE_A)
#define P_SMEM  (2 * TILE_A + 3 * TILE_B2)   // 174080 B

__device__ __forceinline__ void stage_A_f(uint32_t dst, int bm0, int tid) {
    #pragma unroll
    for (int t = 0; t < (BM * 16) / 512; t++) {
        const int i  = tid + t * 512;
        const int r  = i >> 4;
        const int k8 = i & 15;
        cp16(dst + (uint32_t)r * ROWB + (uint32_t)k8 * 16,
             &g_Af16[(size_t)(bm0 + r) * DIN + k8 * 8]);
    }
}
__device__ __forceinline__ void stage_B_f(uint32_t dst, int bn0, int tid) {
    #pragma unroll
    for (int t = 0; t < (BN2 * 16) / 512; t++) {
        const int i  = tid + t * 512;
        const int r  = i >> 4;
        const int k8 = i & 15;
        cp16(dst + (uint32_t)r * ROWB + (uint32_t)k8 * 16,
             &g_Bf16[(size_t)(bn0 + r) * DIN + k8 * 8]);
    }
}

__global__ __launch_bounds__(512, 1) void out_gemm_f(
    const float* __restrict__ bo, float* __restrict__ out)
{
    extern __shared__ char smem[];
    const uint32_t sbase = smem_u32(smem);
    const int tid  = threadIdx.x;
    const int wid  = tid >> 5;
    const int lane = tid & 31;

    const int start = (blockIdx.x * NTILES) / GRID_P;
    const int end   = ((blockIdx.x + 1) * NTILES) / GRID_P;

    stage_A_f(sbase + PO_A, (start >> 5) * BM, tid);
    stage_B_f(sbase + PO_B, (start & 31) * BN2, tid);
    asm volatile("cp.async.commit_group;" ::: "memory");

    const int wm0 = (wid & 3) * 32;
    const int wn0 = (wid >> 2) * 32;
    const int a_row = lane & 15;
    const int a_col = (lane >> 4) * 8;
    const int b_row = ((lane >> 4) * 8) + (lane & 7);   // paired x4 (n16)
    const int b_col = ((lane >> 3) & 1) * 8;

    int abuf = 0;
    int bbuf = 0;
    int bnext = 1;
    for (int t = start; t < end; t++) {
        bool aswitch = false;
        if (t + 1 < end) {
            const int nm = (t + 1) >> 5;
            if (nm != (t >> 5)) {
                stage_A_f(sbase + PO_A + (abuf ^ 1) * TILE_A, nm * BM, tid);
                aswitch = true;
            }
            stage_B_f(sbase + PO_B + bnext * TILE_B2, ((t + 1) & 31) * BN2, tid);
            asm volatile("cp.async.commit_group;" ::: "memory");
            asm volatile("cp.async.wait_group 1;" ::: "memory");
        } else {
            asm volatile("cp.async.wait_group 0;" ::: "memory");
        }
        __syncthreads();

        const uint32_t acur = sbase + PO_A + abuf * TILE_A;
        const uint32_t bcur = sbase + PO_B + bbuf * TILE_B2;

        float acc[2][4][4];
        #pragma unroll
        for (int mf = 0; mf < 2; mf++)
            #pragma unroll
            for (int nf = 0; nf < 4; nf++)
                #pragma unroll
                for (int r = 0; r < 4; r++) acc[mf][nf][r] = 0.f;

        #pragma unroll
        for (int ks = 0; ks < 8; ks++) {
            const int k0 = ks * 16;
            uint32_t aF[2][4], bF[2][4];
            #pragma unroll
            for (int mf = 0; mf < 2; mf++) {
                const uint32_t off = (uint32_t)(wm0 + mf * 16 + a_row) * ROWB
                                   + (uint32_t)(k0 + a_col) * 2;
                ldsm_x4(aF[mf], acur + off);
            }
            #pragma unroll
            for (int p = 0; p < 2; p++) {
                const uint32_t off = (uint32_t)(wn0 + p * 16 + b_row) * ROWB
                                   + (uint32_t)(k0 + b_col) * 2;
                ldsm_x4(bF[p], bcur + off);
            }
            #pragma unroll
            for (int mf = 0; mf < 2; mf++)
                #pragma unroll
                for (int nf = 0; nf < 4; nf++)
                    mma16816h(acc[mf][nf], aF[mf], &bF[nf >> 1][(nf & 1) * 2]);
        }

        const int bm0 = (t >> 5) * BM;
        const int bn0 = (t & 31) * BN2;
        const int er = lane >> 2;
        const int ec = (lane & 3) * 2;
        #pragma unroll
        for (int nf = 0; nf < 4; nf++) {
            const int n = bn0 + wn0 + nf * 8 + ec;
            const float2 bv = *(const float2*)&bo[n];
            #pragma unroll
            for (int mf = 0; mf < 2; mf++) {
                const int m = bm0 + wm0 + mf * 16 + er;
                float2 v0, v1;
                v0.x = acc[mf][nf][0] + bv.x;
                v0.y = acc[mf][nf][1] + bv.y;
                v1.x = acc[mf][nf][2] + bv.x;
                v1.y = acc[mf][nf][3] + bv.y;
                *(float2*)&out[(size_t)m * DOUT + n]       = v0;
                *(float2*)&out[(size_t)(m + 8) * DOUT + n] = v1;
            }
        }
        bbuf = bnext;
        bnext = (bnext == 2) ? 0 : bnext + 1;
        if (aswitch) abuf ^= 1;
    }
}

// ---------------------------------------------------------------------------
// Inputs: nodes, n_node, Wq, bq, Wk, bk, Wv, bv, Wo, bo.
// ---------------------------------------------------------------------------
extern "C" void kernel_launch(void* const* d_in, const int* in_sizes, int n_in,
                              void* d_out, int out_size)
{
    const float* nodes = (const float*)d_in[0];
    const float* Wq    = (const float*)d_in[2];
    const float* bq    = (const float*)d_in[3];
    const float* Wk    = (const float*)d_in[4];
    const float* bk    = (const float*)d_in[5];
    const float* Wv    = (const float*)d_in[6];
    const float* bv    = (const float*)d_in[7];
    const float* Wo    = (const float*)d_in[8];
    const float* bo    = (const float*)d_in[9];
    float* out = (float*)d_out;

    prep_all<<<280, 256>>>(Wq, bq, Wk, bk, Wv, bv, Wo);

    cudaFuncSetAttribute(fused_qkv_attn,
                         cudaFuncAttributeMaxDynamicSharedMemorySize, F_SMEM);
    fused_qkv_attn<<<NODES / FBM, 256, F_SMEM>>>(nodes);

    cudaFuncSetAttribute(out_gemm_f, cudaFuncAttributeMaxDynamicSharedMemorySize,
                         P_SMEM);
    out_gemm_f<<<GRID_P, 512, P_SMEM>>>(bo, out);
}

// round 16
// speedup vs baseline: 1.1089x; 1.1089x over previous
#include <cuda_runtime.h>
#include <cuda_bf16.h>
#include <cuda_fp16.h>
#include <cstdint>

#define NODES   4096
#define GRAPHS  128
#define GSIZE   32
#define DIN     128
#define HK      128     // HEADS*KEY_SIZE
#define QKVN    384     // 3*HK
#define DOUT    4096

// bf16 hi/lo split operands for the precision-critical QKV GEMM
__device__ __align__(16) __nv_bfloat16 g_Whi[QKVN * DIN];    // [Wq|Wk|Wv]^T K-major
__device__ __align__(16) __nv_bfloat16 g_Wlo[QKVN * DIN];
__device__ __align__(16) float         g_bqkv[QKVN];
// fp16 single-precision-pass operands for the output GEMM
__device__ __align__(16) __half        g_Af16[NODES * HK];
__device__ __align__(16) __half        g_Bf16[DOUT * HK];    // WoT K-major

__device__ __forceinline__ uint32_t smem_u32(const void* p) {
    uint32_t a;
    asm("{ .reg .u64 t; cvta.to.shared.u64 t, %1; cvt.u32.u64 %0, t; }"
        : "=r"(a) : "l"(p));
    return a;
}
__device__ __forceinline__ void ldsm_x4(uint32_t* d, uint32_t addr) {
    asm volatile("ldmatrix.sync.aligned.m8n8.x4.shared.b16 {%0,%1,%2,%3}, [%4];"
                 : "=r"(d[0]), "=r"(d[1]), "=r"(d[2]), "=r"(d[3]) : "r"(addr));
}
__device__ __forceinline__ void ldsm_x2(uint32_t* d, uint32_t addr) {
    asm volatile("ldmatrix.sync.aligned.m8n8.x2.shared.b16 {%0,%1}, [%2];"
                 : "=r"(d[0]), "=r"(d[1]) : "r"(addr));
}
__device__ __forceinline__ void mma16816(float* c, const uint32_t* a, const uint32_t* b) {
    asm volatile(
        "mma.sync.aligned.m16n8k16.row.col.f32.bf16.bf16.f32 "
        "{%0,%1,%2,%3}, {%4,%5,%6,%7}, {%8,%9}, {%0,%1,%2,%3};"
        : "+f"(c[0]), "+f"(c[1]), "+f"(c[2]), "+f"(c[3])
        : "r"(a[0]), "r"(a[1]), "r"(a[2]), "r"(a[3]), "r"(b[0]), "r"(b[1]));
}
__device__ __forceinline__ void mma16816h(float* c, const uint32_t* a, const uint32_t* b) {
    asm volatile(
        "mma.sync.aligned.m16n8k16.row.col.f32.f16.f16.f32 "
        "{%0,%1,%2,%3}, {%4,%5,%6,%7}, {%8,%9}, {%0,%1,%2,%3};"
        : "+f"(c[0]), "+f"(c[1]), "+f"(c[2]), "+f"(c[3])
        : "r"(a[0]), "r"(a[1]), "r"(a[2]), "r"(a[3]), "r"(b[0]), "r"(b[1]));
}
__device__ __forceinline__ void cp16(uint32_t smem_addr, const void* gptr) {
    asm volatile("cp.async.cg.shared.global [%0], [%1], 16;"
                 :: "r"(smem_addr), "l"(gptr) : "memory");
}
__device__ __forceinline__ void split_bf16(float x, __nv_bfloat16& h, __nv_bfloat16& l) {
    h = __float2bfloat16(x);
    l = __float2bfloat16(x - __bfloat162float(h));
}

#define ASTRIDE 136                     // 16b elems per smem row (odd 16B units)
#define ROWB    (ASTRIDE * 2)           // 272 bytes per smem row

// ---------------------------------------------------------------------------
// prep_all: weight conversions (no smem, dense occupancy).
// ---------------------------------------------------------------------------
__global__ __launch_bounds__(256) void prep_all(
    const float* __restrict__ Wq, const float* __restrict__ bq,
    const float* __restrict__ Wk, const float* __restrict__ bk,
    const float* __restrict__ Wv, const float* __restrict__ bv,
    const float* __restrict__ Wo)
{
    const int p   = blockIdx.x;
    const int tid = threadIdx.x;

    if (p < 256) {                      // Wo transpose -> fp16, n coalesced
        const int n  = (p & 15) * 256 + tid;
        const int kc = (p >> 4) * 8;
        __align__(16) __half hf[8];
        #pragma unroll
        for (int j = 0; j < 8; j++)
            hf[j] = __float2half(__ldg(&Wo[(size_t)(kc + j) * DOUT + n]));
        *(uint4*)&g_Bf16[(size_t)n * HK + kc] = *(uint4*)hf;
    } else {                            // Wq|Wk|Wv transpose + bias
        const int idx = (p - 256) * 256 + tid;   // [0, 6144)
        const int n   = idx >> 4;                // [0, 384)
        const int kc  = (idx & 15) * 8;
        const float* W = (n < HK) ? Wq : (n < 2 * HK) ? Wk : Wv;
        const float* b = (n < HK) ? bq : (n < 2 * HK) ? bk : bv;
        const int nl = n & (HK - 1);
        __align__(16) __nv_bfloat16 hb[8];
        __align__(16) __nv_bfloat16 lb[8];
        #pragma unroll
        for (int j = 0; j < 8; j++) {
            float x = __ldg(&W[(size_t)(kc + j) * HK + nl]);
            split_bf16(x, hb[j], lb[j]);
        }
        *(uint4*)&g_Whi[(size_t)n * DIN + kc] = *(uint4*)hb;
        *(uint4*)&g_Wlo[(size_t)n * DIN + kc] = *(uint4*)lb;
        if ((idx & 15) == 0) g_bqkv[n] = __ldg(&b[nl]);
    }
}

// ---------------------------------------------------------------------------
// fused_qkv_attn (R14-proven): one CTA per graph (128 CTAs, 256 threads).
//  1) stage the graph's 32x128 node rows as bf16 hi/lo (fused convert)
//  2) bf16x3 MMA against Wqkv in 6 chunks of 64 N-cols (cp.async mod-3 bufs),
//     results (+bias) land as fp32 q|k|v in smem
//  3) per-(head,row) softmax attention straight from smem -> g_Af16
// smem: A 17408 + 3 x B 34816 + qkv 49152 = 171008 B.
// ---------------------------------------------------------------------------
#define FBM   32
#define FBN   64
#define FNC   (QKVN / FBN)              // 6 chunks
#define FA_HI 0
#define FA_LO (FBM * ROWB)              // 8704
#define FB    (2 * FBM * ROWB)          // 17408
#define FB_STR (2 * FBN * ROWB)         // 34816 per buffer (hi then lo)
#define FQKV  (FB + 3 * FB_STR)         // 121856
#define F_SMEM (FQKV + GSIZE * QKVN * 4)   // 171008

__global__ __launch_bounds__(256, 1) void fused_qkv_attn(
    const float* __restrict__ nodes)
{
    extern __shared__ char smem[];
    const uint32_t sbase = smem_u32(smem);
    float* qkv = (float*)(smem + FQKV);
    const int g    = blockIdx.x;
    const int tid  = threadIdx.x;
    const int wid  = tid >> 5;
    const int lane = tid & 31;

    // ---- stage A (32x128 nodes, fused fp32->bf16 hi/lo) ----
    #pragma unroll
    for (int t = 0; t < (FBM * 16) / 256; t++) {
        const int i  = tid + t * 256;
        const int r  = i >> 4;
        const int k8 = i & 15;
        const uint32_t so = (uint32_t)r * ROWB + (uint32_t)k8 * 16;
        const size_t gi = (size_t)(g * GSIZE + r) * DIN + k8 * 8;
        const float4 v0 = *(const float4*)&nodes[gi];
        const float4 v1 = *(const float4*)&nodes[gi + 4];
        const float xs[8] = {v0.x, v0.y, v0.z, v0.w, v1.x, v1.y, v1.z, v1.w};
        __align__(16) __nv_bfloat16 hb[8];
        __align__(16) __nv_bfloat16 lb[8];
        #pragma unroll
        for (int j = 0; j < 8; j++) split_bf16(xs[j], hb[j], lb[j]);
        *(uint4*)(smem + FA_HI + so) = *(uint4*)hb;
        *(uint4*)(smem + FA_LO + so) = *(uint4*)lb;
    }

    // ---- prologue: stage B chunk 0 (hi+lo) into buffer 0 ----
    {
        #pragma unroll
        for (int t = 0; t < (FBN * 16) / 256; t++) {
            const int i  = tid + t * 256;
            const int r  = i >> 4;
            const int k8 = i & 15;
            const uint32_t so = (uint32_t)r * ROWB + (uint32_t)k8 * 16;
            const size_t gb = (size_t)r * DIN + k8 * 8;
            cp16(sbase + FB + so,              &g_Whi[gb]);
            cp16(sbase + FB + FBN * ROWB + so, &g_Wlo[gb]);
        }
        asm volatile("cp.async.commit_group;" ::: "memory");
    }

    const int wn0   = wid * 8;          // each warp owns 8 N-cols of the chunk
    const int a_row = lane & 15;
    const int a_col = (lane >> 4) * 8;
    const int b_row = lane & 7;
    const int b_col = ((lane >> 3) & 1) * 8;

    int bbuf = 0, bnext = 1;
    for (int nc = 0; nc < FNC; nc++) {
        if (nc + 1 < FNC) {
            const uint32_t dst = sbase + FB + bnext * FB_STR;
            #pragma unroll
            for (int t = 0; t < (FBN * 16) / 256; t++) {
                const int i  = tid + t * 256;
                const int r  = i >> 4;
                const int k8 = i & 15;
                const uint32_t so = (uint32_t)r * ROWB + (uint32_t)k8 * 16;
                const size_t gb = (size_t)((nc + 1) * FBN + r) * DIN + k8 * 8;
                cp16(dst + so,              &g_Whi[gb]);
                cp16(dst + FBN * ROWB + so, &g_Wlo[gb]);
            }
            asm volatile("cp.async.commit_group;" ::: "memory");
            asm volatile("cp.async.wait_group 1;" ::: "memory");
        } else {
            asm volatile("cp.async.wait_group 0;" ::: "memory");
        }
        __syncthreads();

        const uint32_t bHiBase = sbase + FB + bbuf * FB_STR;
        const uint32_t bLoBase = bHiBase + FBN * ROWB;

        float acc[2][4];
        #pragma unroll
        for (int mf = 0; mf < 2; mf++)
            #pragma unroll
            for (int r = 0; r < 4; r++) acc[mf][r] = 0.f;

        #pragma unroll
        for (int ks = 0; ks < 8; ks++) {
            const int k0 = ks * 16;
            uint32_t aHi[2][4], aLo[2][4], bHi[2], bLo[2];
            #pragma unroll
            for (int mf = 0; mf < 2; mf++) {
                const uint32_t off = (uint32_t)(mf * 16 + a_row) * ROWB
                                   + (uint32_t)(k0 + a_col) * 2;
                ldsm_x4(aHi[mf], sbase + FA_HI + off);
                ldsm_x4(aLo[mf], sbase + FA_LO + off);
            }
            {
                const uint32_t off = (uint32_t)(wn0 + b_row) * ROWB
                                   + (uint32_t)(k0 + b_col) * 2;
                ldsm_x2(bHi, bHiBase + off);
                ldsm_x2(bLo, bLoBase + off);
            }
            #pragma unroll
            for (int mf = 0; mf < 2; mf++) {
                mma16816(acc[mf], aHi[mf], bHi);
                mma16816(acc[mf], aHi[mf], bLo);
                mma16816(acc[mf], aLo[mf], bHi);
            }
        }

        // write chunk results (+bias) to fp32 qkv smem
        const int er = lane >> 2;
        const int ec = (lane & 3) * 2;
        const int n  = nc * FBN + wn0 + ec;
        const float2 bv = *(const float2*)&g_bqkv[n];
        #pragma unroll
        for (int mf = 0; mf < 2; mf++) {
            const int m = mf * 16 + er;
            float2 v0, v1;
            v0.x = acc[mf][0] + bv.x;
            v0.y = acc[mf][1] + bv.y;
            v1.x = acc[mf][2] + bv.x;
            v1.y = acc[mf][3] + bv.y;
            *(float2*)&qkv[(size_t)m * QKVN + n]       = v0;
            *(float2*)&qkv[(size_t)(m + 8) * QKVN + n] = v1;
        }
        bbuf = bnext;
        bnext = (bnext == 2) ? 0 : bnext + 1;
    }
    __syncthreads();

    // ---- attention phase (threads 0..127), q/k/v fp32 in smem ----
    if (tid < HK) {
        const int h = tid >> 5;
        const int i = tid & 31;
        const float* qrow = qkv + i * QKVN + h * 32;
        float qv[32];
        #pragma unroll
        for (int k4 = 0; k4 < 8; k4++) {
            const float4 t = *(const float4*)&qrow[k4 * 4];
            qv[k4*4+0] = t.x; qv[k4*4+1] = t.y; qv[k4*4+2] = t.z; qv[k4*4+3] = t.w;
        }
        const float scale = 0.17677669529663687f;
        float lo[GSIZE];
        float mx = -1e30f;
        #pragma unroll 4
        for (int j = 0; j < GSIZE; j++) {
            const float* krow = qkv + j * QKVN + HK + h * 32;
            float acc = 0.f;
            #pragma unroll
            for (int k4 = 0; k4 < 8; k4++) {
                const float4 t = *(const float4*)&krow[k4 * 4];
                acc += qv[k4*4+0] * t.x; acc += qv[k4*4+1] * t.y;
                acc += qv[k4*4+2] * t.z; acc += qv[k4*4+3] * t.w;
            }
            acc *= scale;
            lo[j] = acc;
            mx = fmaxf(mx, acc);
        }
        float s = 0.f;
        #pragma unroll
        for (int j = 0; j < GSIZE; j++) { lo[j] = __expf(lo[j] - mx); s += lo[j]; }
        const float inv = 1.f / s;

        float o[32];
        #pragma unroll
        for (int k = 0; k < 32; k++) o[k] = 0.f;
        #pragma unroll 4
        for (int j = 0; j < GSIZE; j++) {
            const float a = lo[j] * inv;
            const float* vrow = qkv + j * QKVN + 2 * HK + h * 32;
            #pragma unroll
            for (int k4 = 0; k4 < 8; k4++) {
                const float4 t = *(const float4*)&vrow[k4 * 4];
                o[k4*4+0] += a * t.x; o[k4*4+1] += a * t.y;
                o[k4*4+2] += a * t.z; o[k4*4+3] += a * t.w;
            }
        }
        const size_t base = (size_t)(g * GSIZE + i) * HK + h * 32;
        #pragma unroll
        for (int c8 = 0; c8 < 4; c8++) {
            __align__(16) __half hf[8];
            #pragma unroll
            for (int j = 0; j < 8; j++) hf[j] = __float2half(o[c8 * 8 + j]);
            *(uint4*)&g_Af16[base + c8 * 8] = *(uint4*)hf;
        }
    }
}

// ---------------------------------------------------------------------------
// Persistent fp16 out_gemm on grid 148: 512 threads, 16 warps = 4M x 4N,
// warp tile 32x32 (B via ldsm_x2 — the proven 24.5us mainloop).
// NEW: depth-2 cp.async pipeline — 4 B buffers (mod-4), wait_group 2.
// A has 2 buffers; <=1 M-switch per CTA so abuf = (t crossed boundary).
// smem: 2 x A(34816) + 4 x B(34816) = 208896 B.
// ---------------------------------------------------------------------------
#define BM 128
#define TILE_A  (BM * ROWB)             // 34816 B
#define BN2     128
#define TILE_B2 (BN2 * ROWB)            // 34816 B
#define GRID_P  148
#define NTILES  1024                    // 32 x 32
#define PO_A    0
#define PO_B    (2 * TILE_A)
#define P_SMEM  (2 * TILE_A + 4 * TILE_B2)   // 208896 B

__device__ __forceinline__ void stage_A_f(uint32_t dst, int bm0, int tid) {
    #pragma unroll
    for (int t = 0; t < (BM * 16) / 512; t++) {
        const int i  = tid + t * 512;
        const int r  = i >> 4;
        const int k8 = i & 15;
        cp16(dst + (uint32_t)r * ROWB + (uint32_t)k8 * 16,
             &g_Af16[(size_t)(bm0 + r) * DIN + k8 * 8]);
    }
}
__device__ __forceinline__ void stage_B_f(uint32_t dst, int bn0, int tid) {
    #pragma unroll
    for (int t = 0; t < (BN2 * 16) / 512; t++) {
        const int i  = tid + t * 512;
        const int r  = i >> 4;
        const int k8 = i & 15;
        cp16(dst + (uint32_t)r * ROWB + (uint32_t)k8 * 16,
             &g_Bf16[(size_t)(bn0 + r) * DIN + k8 * 8]);
    }
}

__global__ __launch_bounds__(512, 1) void out_gemm_f(
    const float* __restrict__ bo, float* __restrict__ out)
{
    extern __shared__ char smem[];
    const uint32_t sbase = smem_u32(smem);
    const int tid  = threadIdx.x;
    const int wid  = tid >> 5;
    const int lane = tid & 31;

    const int start = (blockIdx.x * NTILES) / GRID_P;
    const int end   = ((blockIdx.x + 1) * NTILES) / GRID_P;
    const int m0    = start >> 5;       // first (and maybe only) M-block

    // ---- prologue: stage tiles start and start+1 (one commit each) ----
    stage_A_f(sbase + PO_A, m0 * BM, tid);
    stage_B_f(sbase + PO_B, (start & 31) * BN2, tid);
    asm volatile("cp.async.commit_group;" ::: "memory");
    if (start + 1 < end) {
        if (((start + 1) >> 5) != m0)
            stage_A_f(sbase + PO_A + TILE_A, ((start + 1) >> 5) * BM, tid);
        stage_B_f(sbase + PO_B + TILE_B2, ((start + 1) & 31) * BN2, tid);
        asm volatile("cp.async.commit_group;" ::: "memory");
    }

    const int wm0 = (wid & 3) * 32;
    const int wn0 = (wid >> 2) * 32;
    const int a_row = lane & 15;
    const int a_col = (lane >> 4) * 8;
    const int b_row = lane & 7;
    const int b_col = ((lane >> 3) & 1) * 8;

    for (int t = start; t < end; t++) {
        const int li = t - start;
        if (t + 2 < end) {
            const int tt = t + 2;
            if ((tt >> 5) != ((tt - 1) >> 5))
                stage_A_f(sbase + PO_A + TILE_A, (tt >> 5) * BM, tid);
            stage_B_f(sbase + PO_B + ((li + 2) & 3) * TILE_B2,
                      (tt & 31) * BN2, tid);
            asm volatile("cp.async.commit_group;" ::: "memory");
            asm volatile("cp.async.wait_group 2;" ::: "memory");
        } else if (t + 1 < end) {
            asm volatile("cp.async.wait_group 1;" ::: "memory");
        } else {
            asm volatile("cp.async.wait_group 0;" ::: "memory");
        }
        __syncthreads();   // current tile's data visible to all warps

        const int aidx = ((t >> 5) != m0) ? 1 : 0;
        const uint32_t acur = sbase + PO_A + aidx * TILE_A;
        const uint32_t bcur = sbase + PO_B + (li & 3) * TILE_B2;

        float acc[2][4][4];
        #pragma unroll
        for (int mf = 0; mf < 2; mf++)
            #pragma unroll
            for (int nf = 0; nf < 4; nf++)
                #pragma unroll
                for (int r = 0; r < 4; r++) acc[mf][nf][r] = 0.f;

        #pragma unroll
        for (int ks = 0; ks < 8; ks++) {
            const int k0 = ks * 16;
            uint32_t aF[2][4], bF[4][2];
            #pragma unroll
            for (int mf = 0; mf < 2; mf++) {
                const uint32_t off = (uint32_t)(wm0 + mf * 16 + a_row) * ROWB
                                   + (uint32_t)(k0 + a_col) * 2;
                ldsm_x4(aF[mf], acur + off);
            }
            #pragma unroll
            for (int nf = 0; nf < 4; nf++) {
                const uint32_t off = (uint32_t)(wn0 + nf * 8 + b_row) * ROWB
                                   + (uint32_t)(k0 + b_col) * 2;
                ldsm_x2(bF[nf], bcur + off);
            }
            #pragma unroll
            for (int mf = 0; mf < 2; mf++)
                #pragma unroll
                for (int nf = 0; nf < 4; nf++)
                    mma16816h(acc[mf][nf], aF[mf], bF[nf]);
        }

        const int bm0 = (t >> 5) * BM;
        const int bn0 = (t & 31) * BN2;
        const int er = lane >> 2;
        const int ec = (lane & 3) * 2;
        #pragma unroll
        for (int nf = 0; nf < 4; nf++) {
            const int n = bn0 + wn0 + nf * 8 + ec;
            const float2 bv = *(const float2*)&bo[n];
            #pragma unroll
            for (int mf = 0; mf < 2; mf++) {
                const int m = bm0 + wm0 + mf * 16 + er;
                float2 v0, v1;
                v0.x = acc[mf][nf][0] + bv.x;
                v0.y = acc[mf][nf][1] + bv.y;
                v1.x = acc[mf][nf][2] + bv.x;
                v1.y = acc[mf][nf][3] + bv.y;
                *(float2*)&out[(size_t)m * DOUT + n]       = v0;
                *(float2*)&out[(size_t)(m + 8) * DOUT + n] = v1;
            }
        }
        // no trailing barrier: mod-4 B rotation keeps the prefetch target
        // (li+2) disjoint from current readers (li) and laggards (li-1).
    }
}

// ---------------------------------------------------------------------------
// Inputs: nodes, n_node, Wq, bq, Wk, bk, Wv, bv, Wo, bo.
// ---------------------------------------------------------------------------
extern "C" void kernel_launch(void* const* d_in, const int* in_sizes, int n_in,
                              void* d_out, int out_size)
{
    const float* nodes = (const float*)d_in[0];
    const float* Wq    = (const float*)d_in[2];
    const float* bq    = (const float*)d_in[3];
    const float* Wk    = (const float*)d_in[4];
    const float* bk    = (const float*)d_in[5];
    const float* Wv    = (const float*)d_in[6];
    const float* bv    = (const float*)d_in[7];
    const float* Wo    = (const float*)d_in[8];
    const float* bo    = (const float*)d_in[9];
    float* out = (float*)d_out;

    prep_all<<<280, 256>>>(Wq, bq, Wk, bk, Wv, bv, Wo);

    cudaFuncSetAttribute(fused_qkv_attn,
                         cudaFuncAttributeMaxDynamicSharedMemorySize, F_SMEM);
    fused_qkv_attn<<<GRAPHS, 256, F_SMEM>>>(nodes);

    cudaFuncSetAttribute(out_gemm_f, cudaFuncAttributeMaxDynamicSharedMemorySize,
                         P_SMEM);
    out_gemm_f<<<GRID_P, 512, P_SMEM>>>(bo, out);
}

// round 17
// speedup vs baseline: 1.1572x; 1.0436x over previous
#include <cuda_runtime.h>
#include <cuda_bf16.h>
#include <cuda_fp16.h>
#include <cstdint>

#define NODES   4096
#define GRAPHS  128
#define GSIZE   32
#define DIN     128
#define HK      128     // HEADS*KEY_SIZE
#define QKVN    384     // 3*HK
#define DOUT    4096

// bf16 hi/lo split operands for the precision-critical QKV GEMM
__device__ __align__(16) __nv_bfloat16 g_Whi[QKVN * DIN];    // [Wq|Wk|Wv]^T K-major
__device__ __align__(16) __nv_bfloat16 g_Wlo[QKVN * DIN];
__device__ __align__(16) float         g_bqkv[QKVN];
// fp16 single-precision-pass operands for the output GEMM
__device__ __align__(16) __half        g_Af16[NODES * HK];
__device__ __align__(16) __half        g_Bf16[DOUT * HK];    // WoT K-major

__device__ __forceinline__ uint32_t smem_u32(const void* p) {
    uint32_t a;
    asm("{ .reg .u64 t; cvta.to.shared.u64 t, %1; cvt.u32.u64 %0, t; }"
        : "=r"(a) : "l"(p));
    return a;
}
__device__ __forceinline__ void ldsm_x4(uint32_t* d, uint32_t addr) {
    asm volatile("ldmatrix.sync.aligned.m8n8.x4.shared.b16 {%0,%1,%2,%3}, [%4];"
                 : "=r"(d[0]), "=r"(d[1]), "=r"(d[2]), "=r"(d[3]) : "r"(addr));
}
__device__ __forceinline__ void ldsm_x2(uint32_t* d, uint32_t addr) {
    asm volatile("ldmatrix.sync.aligned.m8n8.x2.shared.b16 {%0,%1}, [%2];"
                 : "=r"(d[0]), "=r"(d[1]) : "r"(addr));
}
__device__ __forceinline__ void mma16816(float* c, const uint32_t* a, const uint32_t* b) {
    asm volatile(
        "mma.sync.aligned.m16n8k16.row.col.f32.bf16.bf16.f32 "
        "{%0,%1,%2,%3}, {%4,%5,%6,%7}, {%8,%9}, {%0,%1,%2,%3};"
        : "+f"(c[0]), "+f"(c[1]), "+f"(c[2]), "+f"(c[3])
        : "r"(a[0]), "r"(a[1]), "r"(a[2]), "r"(a[3]), "r"(b[0]), "r"(b[1]));
}
__device__ __forceinline__ void mma16816h(float* c, const uint32_t* a, const uint32_t* b) {
    asm volatile(
        "mma.sync.aligned.m16n8k16.row.col.f32.f16.f16.f32 "
        "{%0,%1,%2,%3}, {%4,%5,%6,%7}, {%8,%9}, {%0,%1,%2,%3};"
        : "+f"(c[0]), "+f"(c[1]), "+f"(c[2]), "+f"(c[3])
        : "r"(a[0]), "r"(a[1]), "r"(a[2]), "r"(a[3]), "r"(b[0]), "r"(b[1]));
}
__device__ __forceinline__ void cp16(uint32_t smem_addr, const void* gptr) {
    asm volatile("cp.async.cg.shared.global [%0], [%1], 16;"
                 :: "r"(smem_addr), "l"(gptr) : "memory");
}
__device__ __forceinline__ void split_bf16(float x, __nv_bfloat16& h, __nv_bfloat16& l) {
    h = __float2bfloat16(x);
    l = __float2bfloat16(x - __bfloat162float(h));
}

#define ASTRIDE 136                     // 16b elems per smem row (odd 16B units)
#define ROWB    (ASTRIDE * 2)           // 272 bytes per smem row

// ---------------------------------------------------------------------------
// prep_all: weight conversions (no smem, dense occupancy).
//   blocks [0,512)   : Wo -> g_Bf16 (4 k-values/thread for 2x thread count)
//   blocks [512,536) : Wq|Wk|Wv -> g_Whi/g_Wlo (bf16 hi/lo) + bias concat
// ---------------------------------------------------------------------------
__global__ __launch_bounds__(256) void prep_all(
    const float* __restrict__ Wq, const float* __restrict__ bq,
    const float* __restrict__ Wk, const float* __restrict__ bk,
    const float* __restrict__ Wv, const float* __restrict__ bv,
    const float* __restrict__ Wo)
{
    const int p   = blockIdx.x;
    const int tid = threadIdx.x;

    if (p < 512) {                      // Wo transpose -> fp16, n coalesced
        const int n  = (p & 15) * 256 + tid;
        const int kc = (p >> 4) * 4;
        __align__(8) __half hf[4];
        #pragma unroll
        for (int j = 0; j < 4; j++)
            hf[j] = __float2half(__ldg(&Wo[(size_t)(kc + j) * DOUT + n]));
        *(uint2*)&g_Bf16[(size_t)n * HK + kc] = *(uint2*)hf;
    } else {                            // Wq|Wk|Wv transpose + bias
        const int idx = (p - 512) * 256 + tid;   // [0, 6144)
        const int n   = idx >> 4;                // [0, 384)
        const int kc  = (idx & 15) * 8;
        const float* W = (n < HK) ? Wq : (n < 2 * HK) ? Wk : Wv;
        const float* b = (n < HK) ? bq : (n < 2 * HK) ? bk : bv;
        const int nl = n & (HK - 1);
        __align__(16) __nv_bfloat16 hb[8];
        __align__(16) __nv_bfloat16 lb[8];
        #pragma unroll
        for (int j = 0; j < 8; j++) {
            float x = __ldg(&W[(size_t)(kc + j) * HK + nl]);
            split_bf16(x, hb[j], lb[j]);
        }
        *(uint4*)&g_Whi[(size_t)n * DIN + kc] = *(uint4*)hb;
        *(uint4*)&g_Wlo[(size_t)n * DIN + kc] = *(uint4*)lb;
        if ((idx & 15) == 0) g_bqkv[n] = __ldg(&b[nl]);
    }
}

// ---------------------------------------------------------------------------
// fused_qkv_attn: one CTA per graph (128 CTAs, 256 threads).
//  1) stage the graph's 32x128 node rows as bf16 hi/lo (fused convert)
//  2) bf16x3 MMA against Wqkv in 6 chunks of 64 N-cols (cp.async mod-3 bufs);
//     warp layout 2M x 4N (warp tile 16M x 16N) -> A frag re-reads x4 not x8,
//     B frags via paired ldsm_x4.  Results (+bias) -> fp32 q|k|v in smem.
//  3) per-(head,row) softmax attention straight from smem -> g_Af16
// smem: A 17408 + 3 x B 34816 + qkv 49152 = 171008 B.
// ---------------------------------------------------------------------------
#define FBM   32
#define FBN   64
#define FNC   (QKVN / FBN)              // 6 chunks
#define FA_HI 0
#define FA_LO (FBM * ROWB)              // 8704
#define FB    (2 * FBM * ROWB)          // 17408
#define FB_STR (2 * FBN * ROWB)         // 34816 per buffer (hi then lo)
#define FQKV  (FB + 3 * FB_STR)         // 121856
#define F_SMEM (FQKV + GSIZE * QKVN * 4)   // 171008

__global__ __launch_bounds__(256, 1) void fused_qkv_attn(
    const float* __restrict__ nodes)
{
    extern __shared__ char smem[];
    const uint32_t sbase = smem_u32(smem);
    float* qkv = (float*)(smem + FQKV);
    const int g    = blockIdx.x;
    const int tid  = threadIdx.x;
    const int wid  = tid >> 5;
    const int lane = tid & 31;

    // ---- stage A (32x128 nodes, fused fp32->bf16 hi/lo) ----
    #pragma unroll
    for (int t = 0; t < (FBM * 16) / 256; t++) {
        const int i  = tid + t * 256;
        const int r  = i >> 4;
        const int k8 = i & 15;
        const uint32_t so = (uint32_t)r * ROWB + (uint32_t)k8 * 16;
        const size_t gi = (size_t)(g * GSIZE + r) * DIN + k8 * 8;
        const float4 v0 = *(const float4*)&nodes[gi];
        const float4 v1 = *(const float4*)&nodes[gi + 4];
        const float xs[8] = {v0.x, v0.y, v0.z, v0.w, v1.x, v1.y, v1.z, v1.w};
        __align__(16) __nv_bfloat16 hb[8];
        __align__(16) __nv_bfloat16 lb[8];
        #pragma unroll
        for (int j = 0; j < 8; j++) split_bf16(xs[j], hb[j], lb[j]);
        *(uint4*)(smem + FA_HI + so) = *(uint4*)hb;
        *(uint4*)(smem + FA_LO + so) = *(uint4*)lb;
    }

    // ---- prologue: stage B chunk 0 (hi+lo) into buffer 0 ----
    {
        #pragma unroll
        for (int t = 0; t < (FBN * 16) / 256; t++) {
            const int i  = tid + t * 256;
            const int r  = i >> 4;
            const int k8 = i & 15;
            const uint32_t so = (uint32_t)r * ROWB + (uint32_t)k8 * 16;
            const size_t gb = (size_t)r * DIN + k8 * 8;
            cp16(sbase + FB + so,              &g_Whi[gb]);
            cp16(sbase + FB + FBN * ROWB + so, &g_Wlo[gb]);
        }
        asm volatile("cp.async.commit_group;" ::: "memory");
    }

    const int wm0 = (wid & 1) * 16;     // 2 M-groups over 32 rows
    const int wn0 = (wid >> 1) * 16;    // 4 N-groups over 64 cols
    const int a_row = lane & 15;
    const int a_col = (lane >> 4) * 8;
    const int b_row = ((lane >> 4) * 8) + (lane & 7);   // paired x4 (n16)
    const int b_col = ((lane >> 3) & 1) * 8;

    int bbuf = 0, bnext = 1;
    for (int nc = 0; nc < FNC; nc++) {
        if (nc + 1 < FNC) {
            const uint32_t dst = sbase + FB + bnext * FB_STR;
            #pragma unroll
            for (int t = 0; t < (FBN * 16) / 256; t++) {
                const int i  = tid + t * 256;
                const int r  = i >> 4;
                const int k8 = i & 15;
                const uint32_t so = (uint32_t)r * ROWB + (uint32_t)k8 * 16;
                const size_t gb = (size_t)((nc + 1) * FBN + r) * DIN + k8 * 8;
                cp16(dst + so,              &g_Whi[gb]);
                cp16(dst + FBN * ROWB + so, &g_Wlo[gb]);
            }
            asm volatile("cp.async.commit_group;" ::: "memory");
            asm volatile("cp.async.wait_group 1;" ::: "memory");
        } else {
            asm volatile("cp.async.wait_group 0;" ::: "memory");
        }
        __syncthreads();

        const uint32_t bHiBase = sbase + FB + bbuf * FB_STR;
        const uint32_t bLoBase = bHiBase + FBN * ROWB;

        float acc[2][4];                // [nf][reg], warp tile 16M x 16N
        #pragma unroll
        for (int nf = 0; nf < 2; nf++)
            #pragma unroll
            for (int r = 0; r < 4; r++) acc[nf][r] = 0.f;

        #pragma unroll
        for (int ks = 0; ks < 8; ks++) {
            const int k0 = ks * 16;
            uint32_t aHi[4], aLo[4], bHi[4], bLo[4];
            {
                const uint32_t off = (uint32_t)(wm0 + a_row) * ROWB
                                   + (uint32_t)(k0 + a_col) * 2;
                ldsm_x4(aHi, sbase + FA_HI + off);
                ldsm_x4(aLo, sbase + FA_LO + off);
            }
            {
                const uint32_t off = (uint32_t)(wn0 + b_row) * ROWB
                                   + (uint32_t)(k0 + b_col) * 2;
                ldsm_x4(bHi, bHiBase + off);
                ldsm_x4(bLo, bLoBase + off);
            }
            #pragma unroll
            for (int nf = 0; nf < 2; nf++) {
                mma16816(acc[nf], aHi, &bHi[nf * 2]);
                mma16816(acc[nf], aHi, &bLo[nf * 2]);
                mma16816(acc[nf], aLo, &bHi[nf * 2]);
            }
        }

        // write chunk results (+bias) to fp32 qkv smem
        const int er = lane >> 2;
        const int ec = (lane & 3) * 2;
        #pragma unroll
        for (int nf = 0; nf < 2; nf++) {
            const int n = nc * FBN + wn0 + nf * 8 + ec;
            const float2 bv = *(const float2*)&g_bqkv[n];
            const int m = wm0 + er;
            float2 v0, v1;
            v0.x = acc[nf][0] + bv.x;
            v0.y = acc[nf][1] + bv.y;
            v1.x = acc[nf][2] + bv.x;
            v1.y = acc[nf][3] + bv.y;
            *(float2*)&qkv[(size_t)m * QKVN + n]       = v0;
            *(float2*)&qkv[(size_t)(m + 8) * QKVN + n] = v1;
        }
        bbuf = bnext;
        bnext = (bnext == 2) ? 0 : bnext + 1;
    }
    __syncthreads();

    // ---- attention phase (threads 0..127), q/k/v fp32 in smem ----
    if (tid < HK) {
        const int h = tid >> 5;
        const int i = tid & 31;
        const float* qrow = qkv + i * QKVN + h * 32;
        float qv[32];
        #pragma unroll
        for (int k4 = 0; k4 < 8; k4++) {
            const float4 t = *(const float4*)&qrow[k4 * 4];
            qv[k4*4+0] = t.x; qv[k4*4+1] = t.y; qv[k4*4+2] = t.z; qv[k4*4+3] = t.w;
        }
        const float scale = 0.17677669529663687f;
        float lo[GSIZE];
        float mx = -1e30f;
        #pragma unroll 4
        for (int j = 0; j < GSIZE; j++) {
            const float* krow = qkv + j * QKVN + HK + h * 32;
            float acc = 0.f;
            #pragma unroll
            for (int k4 = 0; k4 < 8; k4++) {
                const float4 t = *(const float4*)&krow[k4 * 4];
                acc += qv[k4*4+0] * t.x; acc += qv[k4*4+1] * t.y;
                acc += qv[k4*4+2] * t.z; acc += qv[k4*4+3] * t.w;
            }
            acc *= scale;
            lo[j] = acc;
            mx = fmaxf(mx, acc);
        }
        float s = 0.f;
        #pragma unroll
        for (int j = 0; j < GSIZE; j++) { lo[j] = __expf(lo[j] - mx); s += lo[j]; }
        const float inv = 1.f / s;

        float o[32];
        #pragma unroll
        for (int k = 0; k < 32; k++) o[k] = 0.f;
        #pragma unroll 4
        for (int j = 0; j < GSIZE; j++) {
            const float a = lo[j] * inv;
            const float* vrow = qkv + j * QKVN + 2 * HK + h * 32;
            #pragma unroll
            for (int k4 = 0; k4 < 8; k4++) {
                const float4 t = *(const float4*)&vrow[k4 * 4];
                o[k4*4+0] += a * t.x; o[k4*4+1] += a * t.y;
                o[k4*4+2] += a * t.z; o[k4*4+3] += a * t.w;
            }
        }
        const size_t base = (size_t)(g * GSIZE + i) * HK + h * 32;
        #pragma unroll
        for (int c8 = 0; c8 < 4; c8++) {
            __align__(16) __half hf[8];
            #pragma unroll
            for (int j = 0; j < 8; j++) hf[j] = __float2half(o[c8 * 8 + j]);
            *(uint4*)&g_Af16[base + c8 * 8] = *(uint4*)hf;
        }
    }
}

// ---------------------------------------------------------------------------
// Persistent fp16 out_gemm on grid 148 (R12/R14-proven, FROZEN): 512 threads,
// 16 warps = 4M x 4N, warp tile 32x32, B via ldsm_x2. A double-buffered,
// B triple-buffered (mod-3, no trailing barrier). smem 174080 B.
// ---------------------------------------------------------------------------
#define BM 128
#define TILE_A  (BM * ROWB)             // 34816 B
#define BN2     128
#define TILE_B2 (BN2 * ROWB)            // 34816 B
#define GRID_P  148
#define NTILES  1024                    // 32 x 32
#define PO_A    0
#define PO_B    (2 * TILE_A)
#define P_SMEM  (2 * TILE_A + 3 * TILE_B2)   // 174080 B

__device__ __forceinline__ void stage_A_f(uint32_t dst, int bm0, int tid) {
    #pragma unroll
    for (int t = 0; t < (BM * 16) / 512; t++) {
        const int i  = tid + t * 512;
        const int r  = i >> 4;
        const int k8 = i & 15;
        cp16(dst + (uint32_t)r * ROWB + (uint32_t)k8 * 16,
             &g_Af16[(size_t)(bm0 + r) * DIN + k8 * 8]);
    }
}
__device__ __forceinline__ void stage_B_f(uint32_t dst, int bn0, int tid) {
    #pragma unroll
    for (int t = 0; t < (BN2 * 16) / 512; t++) {
        const int i  = tid + t * 512;
        const int r  = i >> 4;
        const int k8 = i & 15;
        cp16(dst + (uint32_t)r * ROWB + (uint32_t)k8 * 16,
             &g_Bf16[(size_t)(bn0 + r) * DIN + k8 * 8]);
    }
}

__global__ __launch_bounds__(512, 1) void out_gemm_f(
    const float* __restrict__ bo, float* __restrict__ out)
{
    extern __shared__ char smem[];
    const uint32_t sbase = smem_u32(smem);
    const int tid  = threadIdx.x;
    const int wid  = tid >> 5;
    const int lane = tid & 31;

    const int start = (blockIdx.x * NTILES) / GRID_P;
    const int end   = ((blockIdx.x + 1) * NTILES) / GRID_P;

    stage_A_f(sbase + PO_A, (start >> 5) * BM, tid);
    stage_B_f(sbase + PO_B, (start & 31) * BN2, tid);
    asm volatile("cp.async.commit_group;" ::: "memory");

    const int wm0 = (wid & 3) * 32;
    const int wn0 = (wid >> 2) * 32;
    const int a_row = lane & 15;
    const int a_col = (lane >> 4) * 8;
    const int b_row = lane & 7;
    const int b_col = ((lane >> 3) & 1) * 8;

    int abuf = 0;
    int bbuf = 0;
    int bnext = 1;
    for (int t = start; t < end; t++) {
        bool aswitch = false;
        if (t + 1 < end) {
            const int nm = (t + 1) >> 5;
            if (nm != (t >> 5)) {
                stage_A_f(sbase + PO_A + (abuf ^ 1) * TILE_A, nm * BM, tid);
                aswitch = true;
            }
            stage_B_f(sbase + PO_B + bnext * TILE_B2, ((t + 1) & 31) * BN2, tid);
            asm volatile("cp.async.commit_group;" ::: "memory");
            asm volatile("cp.async.wait_group 1;" ::: "memory");
        } else {
            asm volatile("cp.async.wait_group 0;" ::: "memory");
        }
        __syncthreads();

        const uint32_t acur = sbase + PO_A + abuf * TILE_A;
        const uint32_t bcur = sbase + PO_B + bbuf * TILE_B2;

        float acc[2][4][4];
        #pragma unroll
        for (int mf = 0; mf < 2; mf++)
            #pragma unroll
            for (int nf = 0; nf < 4; nf++)
                #pragma unroll
                for (int r = 0; r < 4; r++) acc[mf][nf][r] = 0.f;

        #pragma unroll
        for (int ks = 0; ks < 8; ks++) {
            const int k0 = ks * 16;
            uint32_t aF[2][4], bF[4][2];
            #pragma unroll
            for (int mf = 0; mf < 2; mf++) {
                const uint32_t off = (uint32_t)(wm0 + mf * 16 + a_row) * ROWB
                                   + (uint32_t)(k0 + a_col) * 2;
                ldsm_x4(aF[mf], acur + off);
            }
            #pragma unroll
            for (int nf = 0; nf < 4; nf++) {
                const uint32_t off = (uint32_t)(wn0 + nf * 8 + b_row) * ROWB
                                   + (uint32_t)(k0 + b_col) * 2;
                ldsm_x2(bF[nf], bcur + off);
            }
            #pragma unroll
            for (int mf = 0; mf < 2; mf++)
                #pragma unroll
                for (int nf = 0; nf < 4; nf++)
                    mma16816h(acc[mf][nf], aF[mf], bF[nf]);
        }

        const int bm0 = (t >> 5) * BM;
        const int bn0 = (t & 31) * BN2;
        const int er = lane >> 2;
        const int ec = (lane & 3) * 2;
        #pragma unroll
        for (int nf = 0; nf < 4; nf++) {
            const int n = bn0 + wn0 + nf * 8 + ec;
            const float2 bv = *(const float2*)&bo[n];
            #pragma unroll
            for (int mf = 0; mf < 2; mf++) {
                const int m = bm0 + wm0 + mf * 16 + er;
                float2 v0, v1;
                v0.x = acc[mf][nf][0] + bv.x;
                v0.y = acc[mf][nf][1] + bv.y;
                v1.x = acc[mf][nf][2] + bv.x;
                v1.y = acc[mf][nf][3] + bv.y;
                *(float2*)&out[(size_t)m * DOUT + n]       = v0;
                *(float2*)&out[(size_t)(m + 8) * DOUT + n] = v1;
            }
        }
        bbuf = bnext;
        bnext = (bnext == 2) ? 0 : bnext + 1;
        if (aswitch) abuf ^= 1;
    }
}

// ---------------------------------------------------------------------------
// Inputs: nodes, n_node, Wq, bq, Wk, bk, Wv, bv, Wo, bo.
// ---------------------------------------------------------------------------
extern "C" void kernel_launch(void* const* d_in, const int* in_sizes, int n_in,
                              void* d_out, int out_size)
{
    const float* nodes = (const float*)d_in[0];
    const float* Wq    = (const float*)d_in[2];
    const float* bq    = (const float*)d_in[3];
    const float* Wk    = (const float*)d_in[4];
    const float* bk    = (const float*)d_in[5];
    const float* Wv    = (const float*)d_in[6];
    const float* bv    = (const float*)d_in[7];
    const float* Wo    = (const float*)d_in[8];
    const float* bo    = (const float*)d_in[9];
    float* out = (float*)d_out;

    prep_all<<<536, 256>>>(Wq, bq, Wk, bk, Wv, bv, Wo);

    cudaFuncSetAttribute(fused_qkv_attn,
                         cudaFuncAttributeMaxDynamicSharedMemorySize, F_SMEM);
    fused_qkv_attn<<<GRAPHS, 256, F_SMEM>>>(nodes);

    cudaFuncSetAttribute(out_gemm_f, cudaFuncAttributeMaxDynamicSharedMemorySize,
                         P_SMEM);
    out_gemm_f<<<GRID_P, 512, P_SMEM>>>(bo, out);
}